// round 2
// baseline (speedup 1.0000x reference)
#include <cuda_runtime.h>
#include <cuda_bf16.h>
#include <math.h>
#include <stdint.h>

// Problem constants
#define B_    64
#define T_    2048
#define ENC_  512
#define DEC_  1024
#define HID_  256
#define KCONV 31
#define PADC  15

// GEMM tiling
#define TM 128        // CTA rows (bt)
#define TN 256        // CTA cols (h) == HID
#define KC 64         // K chunk
#define LDS_PAD 8
#define LDA (KC + LDS_PAD)     // 72 elements (bf16)

// ---------------- device scratch (no allocation allowed) ----------------
__device__ __nv_bfloat16 g_Whi[HID_ * ENC_];
__device__ __nv_bfloat16 g_Wlo[HID_ * ENC_];
__device__ __nv_bfloat16 g_F[HID_ * 32];        // fused conv filter, col 31 = 0
__device__ float g_dec[B_ * HID_];              // dec projection + b_enc
__device__ float g_energy[B_ * T_];
__device__ float g_part[B_ * 8 * ENC_];         // att_c partials (t-split)

// ---------------- prep kernels ----------------
__global__ void prep_w(const float* __restrict__ W_enc) {
    int i = blockIdx.x * 256 + threadIdx.x;
    if (i < HID_ * ENC_) {
        float x = W_enc[i];
        __nv_bfloat16 h = __float2bfloat16(x);
        g_Whi[i] = h;
        g_Wlo[i] = __float2bfloat16(x - __bfloat162float(h));
    }
}

__global__ void prep_f(const float* __restrict__ W_att, const float* __restrict__ conv_w) {
    int i = blockIdx.x * 256 + threadIdx.x;
    if (i < HID_ * 32) {
        int h = i >> 5, k = i & 31;
        float s = 0.f;
        if (k < KCONV) {
            #pragma unroll
            for (int c = 0; c < 32; c++) s += W_att[h * 32 + c] * conv_w[c * KCONV + k];
        }
        g_F[i] = __float2bfloat16(s);
    }
}

__global__ void prep_dec(const float* __restrict__ dec_state,
                         const float* __restrict__ W_dec,
                         const float* __restrict__ b_enc) {
    int i = blockIdx.x * 256 + threadIdx.x;
    if (i < B_ * HID_) {
        int b = i >> 8, h = i & 255;
        float s = b_enc[h];
        const float* d = dec_state + b * DEC_;
        const float* w = W_dec + h * DEC_;
        #pragma unroll 4
        for (int c = 0; c < DEC_; c++) s += d[c] * w[c];
        g_dec[i] = s;
    }
}

// ---------------- mma helpers ----------------
__device__ __forceinline__ void mma_bf16(float& c0, float& c1, float& c2, float& c3,
                                         uint32_t a0, uint32_t a1, uint32_t a2, uint32_t a3,
                                         uint32_t b0, uint32_t b1) {
    asm volatile(
        "mma.sync.aligned.m16n8k16.row.col.f32.bf16.bf16.f32 "
        "{%0,%1,%2,%3}, {%4,%5,%6,%7}, {%8,%9}, {%0,%1,%2,%3};"
        : "+f"(c0), "+f"(c1), "+f"(c2), "+f"(c3)
        : "r"(a0), "r"(a1), "r"(a2), "r"(a3), "r"(b0), "r"(b1));
}

// One pass over a (TM x ksteps*16) A tile against a (TN x ksteps*16) W tile.
// A layout: [row][k] stride LDA (bf16). W layout: [n][k] stride LDA (bf16).
__device__ __forceinline__ void mma_pass(const __nv_bfloat16* __restrict__ As,
                                         const __nv_bfloat16* __restrict__ Ws,
                                         int ksteps,
                                         float (&acc)[4][8][4],
                                         int wm, int wn, int lane) {
    int g  = lane >> 2;        // group id
    int tq = lane & 3;
    for (int ks = 0; ks < ksteps; ks++) {
        int kb = ks * 16 + tq * 2;
        uint32_t af[4][4];
        #pragma unroll
        for (int mi = 0; mi < 4; mi++) {
            const __nv_bfloat16* ap = As + (wm * 64 + mi * 16 + g) * LDA + kb;
            af[mi][0] = *(const uint32_t*)(ap);              // (row, k)
            af[mi][1] = *(const uint32_t*)(ap + 8 * LDA);    // (row+8, k)
            af[mi][2] = *(const uint32_t*)(ap + 8);          // (row, k+8)
            af[mi][3] = *(const uint32_t*)(ap + 8 * LDA + 8);// (row+8, k+8)
        }
        #pragma unroll
        for (int ni = 0; ni < 8; ni++) {
            const __nv_bfloat16* bp = Ws + (wn * 64 + ni * 8 + g) * LDA + kb;
            uint32_t b0 = *(const uint32_t*)(bp);
            uint32_t b1 = *(const uint32_t*)(bp + 8);
            #pragma unroll
            for (int mi = 0; mi < 4; mi++) {
                mma_bf16(acc[mi][ni][0], acc[mi][ni][1], acc[mi][ni][2], acc[mi][ni][3],
                         af[mi][0], af[mi][1], af[mi][2], af[mi][3], b0, b1);
            }
        }
    }
}

// ---------------- energy kernel (fused GEMM + conv + tanh-dot) ----------------
#define SMEM_BYTES ((TM * LDA * 2 + TN * LDA * 2) * 2)   // Ahi,Alo,Whi,Wlo = 110592 B

__global__ void __launch_bounds__(256, 1)
energy_kernel(const float* __restrict__ enc,
              const float* __restrict__ prev,
              const float* __restrict__ w_w) {
    extern __shared__ char smraw[];
    __nv_bfloat16* Ahi = (__nv_bfloat16*)smraw;
    __nv_bfloat16* Alo = Ahi + TM * LDA;
    __nv_bfloat16* Whs = Alo + TM * LDA;
    __nv_bfloat16* Wls = Whs + TN * LDA;
    float* red = (float*)smraw;   // reused after final barrier

    const int tid = threadIdx.x;
    const int lane = tid & 31;
    const int warp = tid >> 5;
    const int wm = warp >> 2;     // 0..1
    const int wn = warp & 3;      // 0..3

    const int m0 = blockIdx.x * TM;
    const int b  = m0 >> 11;      // T_=2048
    const int t0 = m0 & (T_ - 1);

    float acc[4][8][4];
    #pragma unroll
    for (int mi = 0; mi < 4; mi++)
        #pragma unroll
        for (int ni = 0; ni < 8; ni++)
            #pragma unroll
            for (int r = 0; r < 4; r++) acc[mi][ni][r] = 0.f;

    const float* encb = enc + ((size_t)b * T_ + t0) * ENC_;

    for (int kc = 0; kc < ENC_; kc += KC) {
        // Load A fp32 tile (128 x 64), convert to hi/lo bf16
        #pragma unroll
        for (int j = 0; j < 8; j++) {
            int li = tid + j * 256;
            int row = li >> 4, c4 = li & 15;
            float4 v = *(const float4*)(encb + (size_t)row * ENC_ + kc + c4 * 4);
            __nv_bfloat16 h0 = __float2bfloat16(v.x);
            __nv_bfloat16 h1 = __float2bfloat16(v.y);
            __nv_bfloat16 h2 = __float2bfloat16(v.z);
            __nv_bfloat16 h3 = __float2bfloat16(v.w);
            __nv_bfloat162 hp0; hp0.x = h0; hp0.y = h1;
            __nv_bfloat162 hp1; hp1.x = h2; hp1.y = h3;
            __nv_bfloat162 lp0 = __floats2bfloat162_rn(v.x - __bfloat162float(h0),
                                                       v.y - __bfloat162float(h1));
            __nv_bfloat162 lp1 = __floats2bfloat162_rn(v.z - __bfloat162float(h2),
                                                       v.w - __bfloat162float(h3));
            __nv_bfloat162* dh = (__nv_bfloat162*)&Ahi[row * LDA + c4 * 4];
            __nv_bfloat162* dl = (__nv_bfloat162*)&Alo[row * LDA + c4 * 4];
            dh[0] = hp0; dh[1] = hp1;
            dl[0] = lp0; dl[1] = lp1;
        }
        // Load W hi/lo tiles (256 x 64 each)
        #pragma unroll
        for (int j = 0; j < 8; j++) {
            int li = tid + j * 256;
            int row = li >> 3, c16 = li & 7;
            *(uint4*)&Whs[row * LDA + c16 * 8] =
                *(const uint4*)&g_Whi[row * ENC_ + kc + c16 * 8];
            *(uint4*)&Wls[row * LDA + c16 * 8] =
                *(const uint4*)&g_Wlo[row * ENC_ + kc + c16 * 8];
        }
        __syncthreads();
        mma_pass(Ahi, Whs, 4, acc, wm, wn, lane);   // hi * hi
        mma_pass(Alo, Whs, 4, acc, wm, wn, lane);   // lo * hi
        mma_pass(Ahi, Wls, 4, acc, wm, wn, lane);   // hi * lo
        __syncthreads();
    }

    // Conv chunk (K=32): shifted prev_att_w against fused filter F
    #pragma unroll
    for (int j = 0; j < 16; j++) {
        int li = tid + j * 256;
        int row = li >> 5, k = li & 31;
        int t = t0 + row - PADC + k;
        float v = (k < KCONV && t >= 0 && t < T_) ? prev[b * T_ + t] : 0.f;
        Ahi[row * LDA + k] = __float2bfloat16(v);
    }
    #pragma unroll
    for (int j = 0; j < 32; j++) {
        int li = tid + j * 256;
        int row = li >> 5, k = li & 31;
        Whs[row * LDA + k] = g_F[row * 32 + k];
    }
    __syncthreads();
    mma_pass(Ahi, Whs, 2, acc, wm, wn, lane);
    __syncthreads();

    // Epilogue: s = acc + dec_full; energy = sum_h w_w[h]*tanh(s)
    float wv[16], dv[16];
    {
        int cbase = wn * 64 + (lane & 3) * 2;
        #pragma unroll
        for (int ni = 0; ni < 8; ni++) {
            int n = cbase + ni * 8;
            wv[2 * ni]     = w_w[n];
            wv[2 * ni + 1] = w_w[n + 1];
            dv[2 * ni]     = g_dec[b * HID_ + n];
            dv[2 * ni + 1] = g_dec[b * HID_ + n + 1];
        }
    }
    #pragma unroll
    for (int mi = 0; mi < 4; mi++) {
        #pragma unroll
        for (int h2 = 0; h2 < 2; h2++) {
            float p = 0.f;
            #pragma unroll
            for (int ni = 0; ni < 8; ni++) {
                #pragma unroll
                for (int j = 0; j < 2; j++) {
                    float s = acc[mi][ni][h2 * 2 + j] + dv[2 * ni + j];
                    p += wv[2 * ni + j] * tanhf(s);
                }
            }
            p += __shfl_xor_sync(0xffffffffu, p, 1);
            p += __shfl_xor_sync(0xffffffffu, p, 2);
            if ((lane & 3) == 0) {
                int row = wm * 64 + mi * 16 + h2 * 8 + (lane >> 2);
                red[row * 4 + wn] = p;
            }
        }
    }
    __syncthreads();
    if (tid < TM) {
        float e = red[tid * 4] + red[tid * 4 + 1] + red[tid * 4 + 2] + red[tid * 4 + 3];
        g_energy[m0 + tid] = e;
    }
}

// ---------------- masked softmax over T ----------------
__global__ void softmax_kernel(const int* __restrict__ text_len, float* __restrict__ out) {
    __shared__ float sh[T_];
    __shared__ float rbuf[256];
    int b = blockIdx.x, tid = threadIdx.x;
    int len = text_len[b];

    float mx = -INFINITY;
    for (int t = tid; t < T_; t += 256) {
        float v = (t < len) ? g_energy[b * T_ + t] : -INFINITY;
        sh[t] = v;
        mx = fmaxf(mx, v);
    }
    rbuf[tid] = mx; __syncthreads();
    for (int s = 128; s > 0; s >>= 1) {
        if (tid < s) rbuf[tid] = fmaxf(rbuf[tid], rbuf[tid + s]);
        __syncthreads();
    }
    mx = rbuf[0];
    __syncthreads();

    float sum = 0.f;
    for (int t = tid; t < T_; t += 256) {
        float v = sh[t];
        float e = (v == -INFINITY) ? 0.f : expf(v - mx);
        sh[t] = e;
        sum += e;
    }
    rbuf[tid] = sum; __syncthreads();
    for (int s = 128; s > 0; s >>= 1) {
        if (tid < s) rbuf[tid] += rbuf[tid + s];
        __syncthreads();
    }
    float inv = 1.f / rbuf[0];

    float* attw = out + B_ * ENC_;
    for (int t = tid; t < T_; t += 256)
        attw[b * T_ + t] = sh[t] * inv;
}

// ---------------- att_c = sum_t att_w[b,t] * enc[b,t,:]  (t-split partials) ----------------
__global__ void attc_part(const float* __restrict__ enc, const float* __restrict__ attw) {
    __shared__ float w[256];
    int ts = blockIdx.x;    // 0..7
    int b  = blockIdx.y;
    int tid = threadIdx.x;  // 128
    w[tid]       = attw[b * T_ + ts * 256 + tid];
    w[tid + 128] = attw[b * T_ + ts * 256 + tid + 128];
    __syncthreads();

    const float4* e4 = (const float4*)(enc + ((size_t)b * T_ + ts * 256) * ENC_) + tid;
    float ax = 0.f, ay = 0.f, az = 0.f, aw = 0.f;
    #pragma unroll 8
    for (int tt = 0; tt < 256; tt++) {
        float4 v = e4[(size_t)tt * (ENC_ / 4)];
        float ww = w[tt];
        ax += ww * v.x; ay += ww * v.y; az += ww * v.z; aw += ww * v.w;
    }
    float4 r; r.x = ax; r.y = ay; r.z = az; r.w = aw;
    *(float4*)&g_part[((b * 8 + ts) * ENC_) + tid * 4] = r;
}

__global__ void attc_reduce(float* __restrict__ out) {
    int i = blockIdx.x * 256 + threadIdx.x;
    if (i < B_ * ENC_) {
        int b = i >> 9, c = i & (ENC_ - 1);
        float s = 0.f;
        #pragma unroll
        for (int ts = 0; ts < 8; ts++) s += g_part[(b * 8 + ts) * ENC_ + c];
        out[i] = s;
    }
}

// ---------------- launch ----------------
extern "C" void kernel_launch(void* const* d_in, const int* in_sizes, int n_in,
                              void* d_out, int out_size) {
    const float* enc       = (const float*)d_in[0];
    const float* dec_state = (const float*)d_in[1];
    const float* prev      = (const float*)d_in[2];
    const int*   text_len  = (const int*)d_in[3];
    const float* W_enc     = (const float*)d_in[4];
    const float* b_enc     = (const float*)d_in[5];
    const float* W_dec     = (const float*)d_in[6];
    const float* W_att     = (const float*)d_in[7];
    const float* conv_w    = (const float*)d_in[8];
    const float* w_w       = (const float*)d_in[9];
    // d_in[10] = w_b: additive constant cancels in softmax; energy itself is not an output.
    float* out = (float*)d_out;

    cudaFuncSetAttribute(energy_kernel, cudaFuncAttributeMaxDynamicSharedMemorySize, SMEM_BYTES);

    prep_w<<<(HID_ * ENC_ + 255) / 256, 256>>>(W_enc);
    prep_f<<<(HID_ * 32 + 255) / 256, 256>>>(W_att, conv_w);
    prep_dec<<<(B_ * HID_ + 255) / 256, 256>>>(dec_state, W_dec, b_enc);

    energy_kernel<<<(B_ * T_) / TM, 256, SMEM_BYTES>>>(enc, prev, w_w);

    softmax_kernel<<<B_, 256>>>(text_len, out);

    attc_part<<<dim3(8, B_), 128>>>(enc, out + B_ * ENC_);
    attc_reduce<<<(B_ * ENC_ + 255) / 256, 256>>>(out);
}